// round 1
// baseline (speedup 1.0000x reference)
#include <cuda_runtime.h>
#include <cuda_bf16.h>
#include <stdint.h>

#define N_NODES  100000
#define N_EDGES  3200000
#define N_FEAT   128
#define HIDDEN   64
#define N_GRAPHS 256

// Padded CSC capacity: E + 3 per node (segment padding to multiple of 4)
#define CSC_CAP  (N_EDGES + 4 * N_NODES)

// ---------------- device scratch (allowed: __device__ globals) ---------------
__device__ __align__(16) static float g_HA[N_NODES * HIDDEN];   // 25.6 MB
__device__ __align__(16) static float g_HB[N_NODES * HIDDEN];   // 25.6 MB
__device__ __align__(16) static int   g_csc[CSC_CAP];           // 14.4 MB (zero-init; padding slots never written)
__device__              static int   g_deg[N_NODES];
__device__              static int   g_rowptr[N_NODES];
__device__              static int   g_cursor[N_NODES];
__device__              static float g_dinv[N_NODES];
__device__              static int   g_bsum[128];

// ---------------- init ----------------
__global__ void k_zero_deg() {
    int i = blockIdx.x * blockDim.x + threadIdx.x;
    if (i < N_NODES) g_deg[i] = 0;
}

// ---------------- degree histogram (in-degree over dst) ----------------
__global__ void k_count(const int* __restrict__ dst) {
    int e = blockIdx.x * blockDim.x + threadIdx.x;
    if (e < N_EDGES) atomicAdd(&g_deg[dst[e]], 1);
}

__global__ void k_dinv() {
    int i = blockIdx.x * blockDim.x + threadIdx.x;
    if (i < N_NODES) {
        float d = (float)(g_deg[i] + 1);   // +1 self loop
        g_dinv[i] = rsqrtf(d);
    }
}

// ---------------- exclusive scan of padded degrees (3 kernels) ----------------
#define SCAN_B 1024
#define SCAN_NB ((N_NODES + SCAN_B - 1) / SCAN_B)   // 98

__global__ void k_scanA() {
    __shared__ int sm[SCAN_B];
    int i = blockIdx.x * SCAN_B + threadIdx.x;
    int v = 0;
    if (i < N_NODES) v = (g_deg[i] + 3) & ~3;       // pad segment to multiple of 4
    sm[threadIdx.x] = v;
    __syncthreads();
    #pragma unroll
    for (int off = 1; off < SCAN_B; off <<= 1) {
        int t = (threadIdx.x >= off) ? sm[threadIdx.x - off] : 0;
        __syncthreads();
        sm[threadIdx.x] += t;
        __syncthreads();
    }
    int inc = sm[threadIdx.x];
    if (i < N_NODES) g_rowptr[i] = inc - v;          // block-local exclusive
    if (threadIdx.x == SCAN_B - 1) g_bsum[blockIdx.x] = inc;
}

__global__ void k_scanB() {
    __shared__ int sm[128];
    int t = threadIdx.x;
    int v = (t < SCAN_NB) ? g_bsum[t] : 0;
    sm[t] = v;
    __syncthreads();
    #pragma unroll
    for (int off = 1; off < 128; off <<= 1) {
        int u = (t >= off) ? sm[t - off] : 0;
        __syncthreads();
        sm[t] += u;
        __syncthreads();
    }
    if (t < SCAN_NB) g_bsum[t] = sm[t] - v;          // exclusive block offsets
}

__global__ void k_scanC() {
    int i = blockIdx.x * blockDim.x + threadIdx.x;
    if (i < N_NODES) {
        int r = g_rowptr[i] + g_bsum[i >> 10];
        g_rowptr[i] = r;
        g_cursor[i] = r;
    }
}

// ---------------- CSC bucket fill ----------------
__global__ void k_fill(const int* __restrict__ src, const int* __restrict__ dst) {
    int e = blockIdx.x * blockDim.x + threadIdx.x;
    if (e < N_EDGES) {
        int d = dst[e];
        int pos = atomicAdd(&g_cursor[d], 1);
        g_csc[pos] = src[e];
    }
}

// ---------------- GEMM: P[row] = (X[row] @ W) * dinv[row] ----------------
// warp-per-row, W staged in smem as float2, x row staged per-warp in smem.
template <int K>
__global__ void k_gemm(const float* __restrict__ X, const float* __restrict__ W,
                       float* __restrict__ P) {
    __shared__ float2 sW[K * 32];          // K x 64 floats
    __shared__ float  sx[8][K];
    const float2* W2 = reinterpret_cast<const float2*>(W);
    for (int t = threadIdx.x; t < K * 32; t += blockDim.x) sW[t] = W2[t];
    __syncthreads();

    int warp = threadIdx.x >> 5;
    int lane = threadIdx.x & 31;
    int nwarps = gridDim.x * (blockDim.x >> 5);

    for (int row = blockIdx.x * 8 + warp; row < N_NODES; row += nwarps) {
        #pragma unroll
        for (int k = lane; k < K; k += 32) sx[warp][k] = X[row * K + k];
        __syncwarp();
        float a0 = 0.f, a1 = 0.f;
        #pragma unroll 8
        for (int k = 0; k < K; k++) {
            float xv = sx[warp][k];
            float2 w = sW[k * 32 + lane];
            a0 += xv * w.x;
            a1 += xv * w.y;
        }
        float s = g_dinv[row];
        reinterpret_cast<float2*>(P)[row * 32 + lane] = make_float2(a0 * s, a1 * s);
        __syncwarp();
    }
}

// ---------------- gather-sum aggregation ----------------
// out[d] = dinv[d] * ( sum_{s in N(d)} P[s] + P[d] ) + b ; optional relu
__global__ void k_gather(const float* __restrict__ Pin, float* __restrict__ Hout,
                         const float* __restrict__ bias, int do_relu) {
    int widx = (blockIdx.x * blockDim.x + threadIdx.x) >> 5;
    if (widx >= N_NODES) return;
    int lane = threadIdx.x & 31;
    int n = widx;

    const float2* P2 = reinterpret_cast<const float2*>(Pin);
    float dn = g_dinv[n];
    int start = g_rowptr[n];
    int cnt = g_deg[n];
    int end = start + cnt;

    float2 self = P2[(size_t)n * 32 + lane];       // P[n] (already * dinv[n])
    float ax = self.x, ay = self.y;

    for (int p = start; p < end; p += 4) {
        int4 s4 = *reinterpret_cast<const int4*>(g_csc + p);   // aligned (start%4==0)
        float2 v0 = P2[(size_t)s4.x * 32 + lane];
        float2 v1 = P2[(size_t)s4.y * 32 + lane];
        float2 v2 = P2[(size_t)s4.z * 32 + lane];
        float2 v3 = P2[(size_t)s4.w * 32 + lane];
        int rem = end - p;
        ax += v0.x; ay += v0.y;
        if (rem > 1) { ax += v1.x; ay += v1.y; }
        if (rem > 2) { ax += v2.x; ay += v2.y; }
        if (rem > 3) { ax += v3.x; ay += v3.y; }
    }

    float2 b = reinterpret_cast<const float2*>(bias)[lane];
    float ox = dn * ax + b.x;
    float oy = dn * ay + b.y;
    if (do_relu) { ox = fmaxf(ox, 0.f); oy = fmaxf(oy, 0.f); }
    reinterpret_cast<float2*>(Hout)[(size_t)n * 32 + lane] = make_float2(ox, oy);
}

// ---------------- pool (mean per graph) + final linear, fused ----------------
__device__ __forceinline__ int lbound(const int* __restrict__ a, int n, int key) {
    int lo = 0, hi = n;
    while (lo < hi) {
        int m = (lo + hi) >> 1;
        if (a[m] < key) lo = m + 1; else hi = m;
    }
    return lo;
}

__global__ void k_pool(const float* __restrict__ H, const int* __restrict__ batch,
                       const float* __restrict__ Wl, const float* __restrict__ bl,
                       float* __restrict__ out) {
    __shared__ float sm[256];
    int g = blockIdx.x;
    int t = threadIdx.x;
    int lo = lbound(batch, N_NODES, g);
    int hi = lbound(batch, N_NODES, g + 1);

    int col = t & 63;
    int part = t >> 6;           // 4 partitions
    float s = 0.f;
    for (int n = lo + part; n < hi; n += 4) s += H[(size_t)n * 64 + col];
    sm[t] = s;
    __syncthreads();
    if (t < 64) {
        float v = sm[t] + sm[t + 64] + sm[t + 128] + sm[t + 192];
        int cnt = hi - lo;
        v /= (float)(cnt > 0 ? cnt : 1);
        sm[t] = v * Wl[t];
    }
    __syncthreads();
    if (t == 0) {
        float r = 0.f;
        #pragma unroll
        for (int c = 0; c < 64; c++) r += sm[c];
        out[g] = r + bl[0];
    }
}

// ---------------- launch ----------------
extern "C" void kernel_launch(void* const* d_in, const int* in_sizes, int n_in,
                              void* d_out, int out_size) {
    const float* x     = (const float*)d_in[0];
    const int*   eidx  = (const int*)d_in[1];
    const int*   batch = (const int*)d_in[2];
    const float* W1    = (const float*)d_in[3];
    const float* b1    = (const float*)d_in[4];
    const float* W2    = (const float*)d_in[5];
    const float* b2    = (const float*)d_in[6];
    const float* Wl    = (const float*)d_in[7];
    const float* bl    = (const float*)d_in[8];
    float* out = (float*)d_out;

    const int* src = eidx;
    const int* dst = eidx + N_EDGES;

    // resolve device-global addresses (host side; graph-capturable, no allocs)
    float *HA, *HB;
    cudaGetSymbolAddress((void**)&HA, g_HA);
    cudaGetSymbolAddress((void**)&HB, g_HB);

    int nThreads = 256;
    int nbNodes = (N_NODES + nThreads - 1) / nThreads;
    int nbEdges = (N_EDGES + nThreads - 1) / nThreads;

    // --- CSC build ---
    k_zero_deg<<<nbNodes, nThreads>>>();
    k_count<<<nbEdges, nThreads>>>(dst);
    k_dinv<<<nbNodes, nThreads>>>();
    k_scanA<<<SCAN_NB, SCAN_B>>>();
    k_scanB<<<1, 128>>>();
    k_scanC<<<nbNodes, nThreads>>>();
    k_fill<<<nbEdges, nThreads>>>(src, dst);

    // --- layer 1: P = (x @ W1) * dinv ; H_B = relu(gather(P) + b1) ---
    k_gemm<N_FEAT><<<296, 256>>>(x, W1, HA);
    k_gather<<<(N_NODES * 32 + 255) / 256, 256>>>(HA, HB, b1, 1);

    // --- layer 2: P = (H_B @ W2) * dinv ; H_B = gather(P) + b2 ---
    k_gemm<HIDDEN><<<296, 256>>>(HB, W2, HA);
    k_gather<<<(N_NODES * 32 + 255) / 256, 256>>>(HA, HB, b2, 0);

    // --- mean pool per graph + linear head ---
    k_pool<<<N_GRAPHS, 256>>>(HB, batch, Wl, bl, out);
}

// round 2
// speedup vs baseline: 1.3944x; 1.3944x over previous
#include <cuda_runtime.h>
#include <cuda_bf16.h>
#include <stdint.h>

#define N_NODES  100000
#define N_EDGES  3200000
#define N_FEAT   128
#define HIDDEN   64
#define N_GRAPHS 256

// Padded CSC capacity: E + 3 per node (segment padding to multiple of 4)
#define CSC_CAP  (N_EDGES + 4 * N_NODES)

// ---------------- device scratch ----------------
__device__ __align__(16) static __nv_bfloat162 g_P [N_NODES * 32];  // 12.8 MB messages
__device__ __align__(16) static __nv_bfloat162 g_H1[N_NODES * 32];  // 12.8 MB layer-1 out
__device__ __align__(16) static float          g_H2[N_NODES * 64];  // 25.6 MB layer-2 out
__device__ __align__(16) static int   g_csc[CSC_CAP];               // padding slots stay 0
__device__              static int   g_deg[N_NODES];
__device__              static int   g_rowptr[N_NODES];
__device__              static int   g_cursor[N_NODES];
__device__              static float g_dinv[N_NODES];
__device__              static int   g_bsum[128];

// ---------------- init / degree ----------------
__global__ void k_zero_deg() {
    int i = blockIdx.x * blockDim.x + threadIdx.x;
    if (i < N_NODES) g_deg[i] = 0;
}

__global__ void k_count(const int* __restrict__ dst) {
    int e = blockIdx.x * blockDim.x + threadIdx.x;
    if (e < N_EDGES) atomicAdd(&g_deg[dst[e]], 1);
}

// ---------------- exclusive scan of padded degrees (+ dinv fused) ----------------
#define SCAN_B 1024
#define SCAN_NB ((N_NODES + SCAN_B - 1) / SCAN_B)   // 98

__global__ void k_scanA() {
    __shared__ int sm[SCAN_B];
    int i = blockIdx.x * SCAN_B + threadIdx.x;
    int v = 0;
    if (i < N_NODES) {
        int d = g_deg[i];
        g_dinv[i] = rsqrtf((float)(d + 1));          // fused dinv (self-loop +1)
        v = (d + 3) & ~3;                            // pad segment to multiple of 4
    }
    sm[threadIdx.x] = v;
    __syncthreads();
    #pragma unroll
    for (int off = 1; off < SCAN_B; off <<= 1) {
        int t = (threadIdx.x >= off) ? sm[threadIdx.x - off] : 0;
        __syncthreads();
        sm[threadIdx.x] += t;
        __syncthreads();
    }
    int inc = sm[threadIdx.x];
    if (i < N_NODES) g_rowptr[i] = inc - v;
    if (threadIdx.x == SCAN_B - 1) g_bsum[blockIdx.x] = inc;
}

__global__ void k_scanB() {
    __shared__ int sm[128];
    int t = threadIdx.x;
    int v = (t < SCAN_NB) ? g_bsum[t] : 0;
    sm[t] = v;
    __syncthreads();
    #pragma unroll
    for (int off = 1; off < 128; off <<= 1) {
        int u = (t >= off) ? sm[t - off] : 0;
        __syncthreads();
        sm[t] += u;
        __syncthreads();
    }
    if (t < SCAN_NB) g_bsum[t] = sm[t] - v;
}

__global__ void k_scanC() {
    int i = blockIdx.x * blockDim.x + threadIdx.x;
    if (i < N_NODES) {
        int r = g_rowptr[i] + g_bsum[i >> 10];
        g_rowptr[i] = r;
        g_cursor[i] = r;
    }
}

__global__ void k_fill(const int* __restrict__ src, const int* __restrict__ dst) {
    int e = blockIdx.x * blockDim.x + threadIdx.x;
    if (e < N_EDGES) {
        int d = dst[e];
        int pos = atomicAdd(&g_cursor[d], 1);
        g_csc[pos] = src[e];
    }
}

// ---------------- f32x2 helpers ----------------
__device__ __forceinline__ unsigned long long dup_f32(float x) {
    unsigned long long r;
    unsigned xb = __float_as_uint(x);
    asm("mov.b64 %0, {%1, %1};" : "=l"(r) : "r"(xb));
    return r;
}
__device__ __forceinline__ void fma2(unsigned long long& acc, unsigned long long a,
                                     unsigned long long b) {
    asm("fma.rn.f32x2 %0, %1, %2, %0;" : "+l"(acc) : "l"(a), "l"(b));
}
__device__ __forceinline__ void unpack2(unsigned long long v, float& lo, float& hi) {
    asm("mov.b64 {%0, %1}, %2;" : "=f"(lo), "=f"(hi) : "l"(v));
}

__device__ __forceinline__ void emit_row(int row, int lane, float c0, float c1) {
    if (row < N_NODES) {
        float s = g_dinv[row];
        g_P[row * 32 + lane] = __floats2bfloat162_rn(c0 * s, c1 * s);
    }
}

// ---------------- GEMM1: P = (X[fp32, K=128] @ W1) * dinv, bf16 out ----------------
// warp = 8 rows; lane = 2 cols; packed f32x2 FMA; dynamic smem 64KB.
__global__ void k_gemm1(const float* __restrict__ X, const float* __restrict__ W) {
    extern __shared__ unsigned char dyn[];
    float2*     sW = (float2*)dyn;                         // 128*32 float2 = 32KB
    ulonglong2* sx = (ulonglong2*)(dyn + 32768);           // 8 warps * 256 entries = 32KB
    const float2* W2 = (const float2*)W;
    for (int t = threadIdx.x; t < 128 * 32; t += 256) sW[t] = W2[t];
    __syncthreads();

    int warp = threadIdx.x >> 5, lane = threadIdx.x & 31;
    ulonglong2* sxA = sx + warp * 256;   // rows 0-3, [128]
    ulonglong2* sxB = sxA + 128;         // rows 4-7, [128]
    const int NG = (N_NODES + 63) >> 6;  // 64-row groups

    for (int g = blockIdx.x; g < NG; g += gridDim.x) {
        int row0 = g * 64 + warp * 8;
        // stage: transpose 8 rows into per-k float4 pairs via STS.128
        #pragma unroll
        for (int j = 0; j < 4; j++) {
            int k = lane + 32 * j;
            float v[8];
            #pragma unroll
            for (int r = 0; r < 8; r++) {
                int rr = row0 + r; if (rr >= N_NODES) rr = N_NODES - 1;
                v[r] = X[(size_t)rr * 128 + k];
            }
            float4 fa = make_float4(v[0], v[1], v[2], v[3]);
            float4 fb = make_float4(v[4], v[5], v[6], v[7]);
            sxA[k] = *reinterpret_cast<ulonglong2*>(&fa);
            sxB[k] = *reinterpret_cast<ulonglong2*>(&fb);
        }
        __syncwarp();

        unsigned long long acc[8];
        #pragma unroll
        for (int i = 0; i < 8; i++) acc[i] = 0ull;   // (0.f,0.f)

        #pragma unroll 4
        for (int k = 0; k < 128; k++) {
            float2 w = sW[k * 32 + lane];
            unsigned long long wxx = dup_f32(w.x);
            unsigned long long wyy = dup_f32(w.y);
            ulonglong2 a = sxA[k];        // broadcast LDS.128
            ulonglong2 b = sxB[k];
            fma2(acc[0], a.x, wxx);  // rows01 c0
            fma2(acc[1], a.y, wxx);  // rows23 c0
            fma2(acc[2], a.x, wyy);  // rows01 c1
            fma2(acc[3], a.y, wyy);  // rows23 c1
            fma2(acc[4], b.x, wxx);  // rows45 c0
            fma2(acc[5], b.y, wxx);
            fma2(acc[6], b.x, wyy);  // rows45 c1
            fma2(acc[7], b.y, wyy);
        }

        #pragma unroll
        for (int h = 0; h < 4; h++) {
            int ia = (h < 2) ? h : h + 2;   // c0 accs: 0,1,4,5
            int ib = ia + 2;                // c1 accs: 2,3,6,7
            float l0, h0, l1, h1;
            unpack2(acc[ia], l0, h0);
            unpack2(acc[ib], l1, h1);
            emit_row(row0 + 2 * h,     lane, l0, l1);
            emit_row(row0 + 2 * h + 1, lane, h0, h1);
        }
        __syncwarp();
    }
}

// ---------------- GEMM2: P = (H1[bf16, K=64] @ W2) * dinv, bf16 out ----------------
__global__ void k_gemm2(const float* __restrict__ W) {
    __shared__ float2     sW[64 * 32];      // 16KB
    __shared__ ulonglong2 sx[8 * 128];      // per warp: A[64], B[64] = 16KB
    const float2* W2 = (const float2*)W;
    for (int t = threadIdx.x; t < 64 * 32; t += 256) sW[t] = W2[t];
    __syncthreads();

    int warp = threadIdx.x >> 5, lane = threadIdx.x & 31;
    ulonglong2* sxA = sx + warp * 128;
    ulonglong2* sxB = sxA + 64;
    const int NG = (N_NODES + 63) >> 6;

    for (int g = blockIdx.x; g < NG; g += gridDim.x) {
        int row0 = g * 64 + warp * 8;
        // stage: each lane owns cols k=2*lane, 2*lane+1 of all 8 rows
        {
            float2 f[8];
            #pragma unroll
            for (int r = 0; r < 8; r++) {
                int rr = row0 + r; if (rr >= N_NODES) rr = N_NODES - 1;
                f[r] = __bfloat1622float2(g_H1[rr * 32 + lane]);
            }
            float4 a0 = make_float4(f[0].x, f[1].x, f[2].x, f[3].x);
            float4 a1 = make_float4(f[0].y, f[1].y, f[2].y, f[3].y);
            float4 b0 = make_float4(f[4].x, f[5].x, f[6].x, f[7].x);
            float4 b1 = make_float4(f[4].y, f[5].y, f[6].y, f[7].y);
            sxA[2 * lane]     = *reinterpret_cast<ulonglong2*>(&a0);
            sxA[2 * lane + 1] = *reinterpret_cast<ulonglong2*>(&a1);
            sxB[2 * lane]     = *reinterpret_cast<ulonglong2*>(&b0);
            sxB[2 * lane + 1] = *reinterpret_cast<ulonglong2*>(&b1);
        }
        __syncwarp();

        unsigned long long acc[8];
        #pragma unroll
        for (int i = 0; i < 8; i++) acc[i] = 0ull;

        #pragma unroll 4
        for (int k = 0; k < 64; k++) {
            float2 w = sW[k * 32 + lane];
            unsigned long long wxx = dup_f32(w.x);
            unsigned long long wyy = dup_f32(w.y);
            ulonglong2 a = sxA[k];
            ulonglong2 b = sxB[k];
            fma2(acc[0], a.x, wxx);
            fma2(acc[1], a.y, wxx);
            fma2(acc[2], a.x, wyy);
            fma2(acc[3], a.y, wyy);
            fma2(acc[4], b.x, wxx);
            fma2(acc[5], b.y, wxx);
            fma2(acc[6], b.x, wyy);
            fma2(acc[7], b.y, wyy);
        }

        #pragma unroll
        for (int h = 0; h < 4; h++) {
            int ia = (h < 2) ? h : h + 2;
            int ib = ia + 2;
            float l0, h0, l1, h1;
            unpack2(acc[ia], l0, h0);
            unpack2(acc[ib], l1, h1);
            emit_row(row0 + 2 * h,     lane, l0, l1);
            emit_row(row0 + 2 * h + 1, lane, h0, h1);
        }
        __syncwarp();
    }
}

// ---------------- gather-sum aggregation (bf16 messages, fp32 accumulate) ---------
// out[d] = dinv[d] * ( sum_{s in N(d)} P[s] + P[d] ) + b ; optional relu
template <int RELU, int OUT_BF16>
__global__ void k_gather(void* __restrict__ Hout, const float* __restrict__ bias) {
    int widx = (blockIdx.x * blockDim.x + threadIdx.x) >> 5;
    if (widx >= N_NODES) return;
    int lane = threadIdx.x & 31;

    float dn = g_dinv[widx];
    int start = g_rowptr[widx];
    int cnt = g_deg[widx];
    int end = start + cnt;

    float2 acc = __bfloat1622float2(g_P[widx * 32 + lane]);   // self term

    for (int p = start; p < end; p += 4) {
        int4 s4 = *reinterpret_cast<const int4*>(g_csc + p);  // aligned
        float2 v0 = __bfloat1622float2(g_P[(size_t)s4.x * 32 + lane]);
        float2 v1 = __bfloat1622float2(g_P[(size_t)s4.y * 32 + lane]);
        float2 v2 = __bfloat1622float2(g_P[(size_t)s4.z * 32 + lane]);
        float2 v3 = __bfloat1622float2(g_P[(size_t)s4.w * 32 + lane]);
        int rem = end - p;
        acc.x += v0.x; acc.y += v0.y;
        if (rem > 1) { acc.x += v1.x; acc.y += v1.y; }
        if (rem > 2) { acc.x += v2.x; acc.y += v2.y; }
        if (rem > 3) { acc.x += v3.x; acc.y += v3.y; }
    }

    float2 b = reinterpret_cast<const float2*>(bias)[lane];
    float ox = dn * acc.x + b.x;
    float oy = dn * acc.y + b.y;
    if (RELU) { ox = fmaxf(ox, 0.f); oy = fmaxf(oy, 0.f); }
    if (OUT_BF16)
        ((__nv_bfloat162*)Hout)[widx * 32 + lane] = __floats2bfloat162_rn(ox, oy);
    else
        ((float2*)Hout)[widx * 32 + lane] = make_float2(ox, oy);
}

// ---------------- pool (mean per graph) + final linear ----------------
__device__ __forceinline__ int lbound(const int* __restrict__ a, int n, int key) {
    int lo = 0, hi = n;
    while (lo < hi) {
        int m = (lo + hi) >> 1;
        if (a[m] < key) lo = m + 1; else hi = m;
    }
    return lo;
}

__global__ void k_pool(const int* __restrict__ batch,
                       const float* __restrict__ Wl, const float* __restrict__ bl,
                       float* __restrict__ out) {
    __shared__ float sm[256];
    int g = blockIdx.x;
    int t = threadIdx.x;
    int lo = lbound(batch, N_NODES, g);
    int hi = lbound(batch, N_NODES, g + 1);

    int col = t & 63;
    int part = t >> 6;
    float s = 0.f;
    for (int n = lo + part; n < hi; n += 4) s += g_H2[(size_t)n * 64 + col];
    sm[t] = s;
    __syncthreads();
    if (t < 64) {
        float v = sm[t] + sm[t + 64] + sm[t + 128] + sm[t + 192];
        int cnt = hi - lo;
        v /= (float)(cnt > 0 ? cnt : 1);
        sm[t] = v * Wl[t];
    }
    __syncthreads();
    if (t == 0) {
        float r = 0.f;
        #pragma unroll
        for (int c = 0; c < 64; c++) r += sm[c];
        out[g] = r + bl[0];
    }
}

// ---------------- launch ----------------
extern "C" void kernel_launch(void* const* d_in, const int* in_sizes, int n_in,
                              void* d_out, int out_size) {
    const float* x     = (const float*)d_in[0];
    const int*   eidx  = (const int*)d_in[1];
    const int*   batch = (const int*)d_in[2];
    const float* W1    = (const float*)d_in[3];
    const float* b1    = (const float*)d_in[4];
    const float* W2    = (const float*)d_in[5];
    const float* b2    = (const float*)d_in[6];
    const float* Wl    = (const float*)d_in[7];
    const float* bl    = (const float*)d_in[8];
    float* out = (float*)d_out;

    const int* src = eidx;
    const int* dst = eidx + N_EDGES;

    float *H1p, *H2p;  // only for typed args where needed
    (void)H1p; (void)H2p;

    // gemm1 needs 64KB dynamic smem (idempotent; not a graph node)
    cudaFuncSetAttribute(k_gemm1, cudaFuncAttributeMaxDynamicSharedMemorySize, 65536);

    int nThreads = 256;
    int nbNodes = (N_NODES + nThreads - 1) / nThreads;
    int nbEdges = (N_EDGES + nThreads - 1) / nThreads;

    // --- CSC build ---
    k_zero_deg<<<nbNodes, nThreads>>>();
    k_count<<<nbEdges, nThreads>>>(dst);
    k_scanA<<<SCAN_NB, SCAN_B>>>();
    k_scanB<<<1, 128>>>();
    k_scanC<<<nbNodes, nThreads>>>();
    k_fill<<<nbEdges, nThreads>>>(src, dst);

    // --- layer 1 ---
    k_gemm1<<<444, 256, 65536>>>(x, W1);
    float* H1v; cudaGetSymbolAddress((void**)&H1v, g_H1);
    k_gather<1, 1><<<(N_NODES * 32 + 255) / 256, 256>>>((void*)H1v, b1);

    // --- layer 2 ---
    k_gemm2<<<592, 256>>>(W2);
    float* H2v; cudaGetSymbolAddress((void**)&H2v, g_H2);
    k_gather<0, 0><<<(N_NODES * 32 + 255) / 256, 256>>>((void*)H2v, b2);

    // --- pool + head ---
    k_pool<<<N_GRAPHS, 256>>>(batch, Wl, bl, out);
}

// round 3
// speedup vs baseline: 1.3946x; 1.0001x over previous
#include <cuda_runtime.h>
#include <cuda_bf16.h>
#include <stdint.h>

#define N_NODES  100000
#define N_EDGES  3200000
#define N_FEAT   128
#define HIDDEN   64
#define N_GRAPHS 256

// Padded CSC capacity: E + 3 per node (segment padding to multiple of 4)
#define CSC_CAP  (N_EDGES + 4 * N_NODES)

// ---------------- device scratch ----------------
__device__ __align__(16) static __nv_bfloat162 g_P [N_NODES * 32];  // 12.8 MB messages
__device__ __align__(16) static __nv_bfloat162 g_H1[N_NODES * 32];  // 12.8 MB layer-1 out
__device__ __align__(16) static float          g_H2[N_NODES * 64];  // 25.6 MB layer-2 out
__device__ __align__(16) static int   g_csc[CSC_CAP];               // padding slots stay 0
__device__              static int   g_deg[N_NODES];
__device__              static int   g_rowptr[N_NODES];
__device__              static int   g_cursor[N_NODES];
__device__              static float g_dinv[N_NODES];
__device__              static int   g_bsum[128];

// ---------------- init / degree ----------------
__global__ void k_zero_deg() {
    int i = blockIdx.x * blockDim.x + threadIdx.x;
    if (i < N_NODES) g_deg[i] = 0;
}

__global__ void k_count(const int* __restrict__ dst) {
    int e = blockIdx.x * blockDim.x + threadIdx.x;
    if (e < N_EDGES) atomicAdd(&g_deg[dst[e]], 1);
}

// ---------------- exclusive scan of padded degrees (+ dinv fused) ----------------
#define SCAN_B 1024
#define SCAN_NB ((N_NODES + SCAN_B - 1) / SCAN_B)   // 98

__global__ void k_scanA() {
    __shared__ int sm[SCAN_B];
    int i = blockIdx.x * SCAN_B + threadIdx.x;
    int v = 0;
    if (i < N_NODES) {
        int d = g_deg[i];
        g_dinv[i] = rsqrtf((float)(d + 1));          // fused dinv (self-loop +1)
        v = (d + 3) & ~3;                            // pad segment to multiple of 4
    }
    sm[threadIdx.x] = v;
    __syncthreads();
    #pragma unroll
    for (int off = 1; off < SCAN_B; off <<= 1) {
        int t = (threadIdx.x >= off) ? sm[threadIdx.x - off] : 0;
        __syncthreads();
        sm[threadIdx.x] += t;
        __syncthreads();
    }
    int inc = sm[threadIdx.x];
    if (i < N_NODES) g_rowptr[i] = inc - v;
    if (threadIdx.x == SCAN_B - 1) g_bsum[blockIdx.x] = inc;
}

__global__ void k_scanB() {
    __shared__ int sm[128];
    int t = threadIdx.x;
    int v = (t < SCAN_NB) ? g_bsum[t] : 0;
    sm[t] = v;
    __syncthreads();
    #pragma unroll
    for (int off = 1; off < 128; off <<= 1) {
        int u = (t >= off) ? sm[t - off] : 0;
        __syncthreads();
        sm[t] += u;
        __syncthreads();
    }
    if (t < SCAN_NB) g_bsum[t] = sm[t] - v;
}

__global__ void k_scanC() {
    int i = blockIdx.x * blockDim.x + threadIdx.x;
    if (i < N_NODES) {
        int r = g_rowptr[i] + g_bsum[i >> 10];
        g_rowptr[i] = r;
        g_cursor[i] = r;
    }
}

__global__ void k_fill(const int* __restrict__ src, const int* __restrict__ dst) {
    int e = blockIdx.x * blockDim.x + threadIdx.x;
    if (e < N_EDGES) {
        int d = dst[e];
        int pos = atomicAdd(&g_cursor[d], 1);
        g_csc[pos] = src[e];
    }
}

// ---------------- f32x2 helpers ----------------
__device__ __forceinline__ unsigned long long dup_f32(float x) {
    unsigned long long r;
    unsigned xb = __float_as_uint(x);
    asm("mov.b64 %0, {%1, %1};" : "=l"(r) : "r"(xb));
    return r;
}
__device__ __forceinline__ void fma2(unsigned long long& acc, unsigned long long a,
                                     unsigned long long b) {
    asm("fma.rn.f32x2 %0, %1, %2, %0;" : "+l"(acc) : "l"(a), "l"(b));
}
__device__ __forceinline__ void unpack2(unsigned long long v, float& lo, float& hi) {
    asm("mov.b64 {%0, %1}, %2;" : "=f"(lo), "=f"(hi) : "l"(v));
}

__device__ __forceinline__ void emit_row(int row, int lane, float c0, float c1) {
    if (row < N_NODES) {
        float s = g_dinv[row];
        g_P[row * 32 + lane] = __floats2bfloat162_rn(c0 * s, c1 * s);
    }
}

// ---------------- GEMM1: P = (X[fp32, K=128] @ W1) * dinv, bf16 out ----------------
// warp = 8 rows; lane = 2 cols; packed f32x2 FMA; dynamic smem 64KB.
__global__ void k_gemm1(const float* __restrict__ X, const float* __restrict__ W) {
    extern __shared__ unsigned char dyn[];
    float2*     sW = (float2*)dyn;                         // 128*32 float2 = 32KB
    ulonglong2* sx = (ulonglong2*)(dyn + 32768);           // 8 warps * 256 entries = 32KB
    const float2* W2 = (const float2*)W;
    for (int t = threadIdx.x; t < 128 * 32; t += 256) sW[t] = W2[t];
    __syncthreads();

    int warp = threadIdx.x >> 5, lane = threadIdx.x & 31;
    ulonglong2* sxA = sx + warp * 256;   // rows 0-3, [128]
    ulonglong2* sxB = sxA + 128;         // rows 4-7, [128]
    const int NG = (N_NODES + 63) >> 6;  // 64-row groups

    for (int g = blockIdx.x; g < NG; g += gridDim.x) {
        int row0 = g * 64 + warp * 8;
        // stage: transpose 8 rows into per-k float4 pairs via STS.128
        #pragma unroll
        for (int j = 0; j < 4; j++) {
            int k = lane + 32 * j;
            float v[8];
            #pragma unroll
            for (int r = 0; r < 8; r++) {
                int rr = row0 + r; if (rr >= N_NODES) rr = N_NODES - 1;
                v[r] = X[(size_t)rr * 128 + k];
            }
            float4 fa = make_float4(v[0], v[1], v[2], v[3]);
            float4 fb = make_float4(v[4], v[5], v[6], v[7]);
            sxA[k] = *reinterpret_cast<ulonglong2*>(&fa);
            sxB[k] = *reinterpret_cast<ulonglong2*>(&fb);
        }
        __syncwarp();

        unsigned long long acc[8];
        #pragma unroll
        for (int i = 0; i < 8; i++) acc[i] = 0ull;   // (0.f,0.f)

        #pragma unroll 4
        for (int k = 0; k < 128; k++) {
            float2 w = sW[k * 32 + lane];
            unsigned long long wxx = dup_f32(w.x);
            unsigned long long wyy = dup_f32(w.y);
            ulonglong2 a = sxA[k];        // broadcast LDS.128
            ulonglong2 b = sxB[k];
            fma2(acc[0], a.x, wxx);  // rows01 c0
            fma2(acc[1], a.y, wxx);  // rows23 c0
            fma2(acc[2], a.x, wyy);  // rows01 c1
            fma2(acc[3], a.y, wyy);  // rows23 c1
            fma2(acc[4], b.x, wxx);  // rows45 c0
            fma2(acc[5], b.y, wxx);
            fma2(acc[6], b.x, wyy);  // rows45 c1
            fma2(acc[7], b.y, wyy);
        }

        #pragma unroll
        for (int h = 0; h < 4; h++) {
            int ia = (h < 2) ? h : h + 2;   // c0 accs: 0,1,4,5
            int ib = ia + 2;                // c1 accs: 2,3,6,7
            float l0, h0, l1, h1;
            unpack2(acc[ia], l0, h0);
            unpack2(acc[ib], l1, h1);
            emit_row(row0 + 2 * h,     lane, l0, l1);
            emit_row(row0 + 2 * h + 1, lane, h0, h1);
        }
        __syncwarp();
    }
}

// ---------------- GEMM2: P = (H1[bf16, K=64] @ W2) * dinv, bf16 out ----------------
__global__ void k_gemm2(const float* __restrict__ W) {
    __shared__ float2     sW[64 * 32];      // 16KB
    __shared__ ulonglong2 sx[8 * 128];      // per warp: A[64], B[64] = 16KB
    const float2* W2 = (const float2*)W;
    for (int t = threadIdx.x; t < 64 * 32; t += 256) sW[t] = W2[t];
    __syncthreads();

    int warp = threadIdx.x >> 5, lane = threadIdx.x & 31;
    ulonglong2* sxA = sx + warp * 128;
    ulonglong2* sxB = sxA + 64;
    const int NG = (N_NODES + 63) >> 6;

    for (int g = blockIdx.x; g < NG; g += gridDim.x) {
        int row0 = g * 64 + warp * 8;
        // stage: each lane owns cols k=2*lane, 2*lane+1 of all 8 rows
        {
            float2 f[8];
            #pragma unroll
            for (int r = 0; r < 8; r++) {
                int rr = row0 + r; if (rr >= N_NODES) rr = N_NODES - 1;
                f[r] = __bfloat1622float2(g_H1[rr * 32 + lane]);
            }
            float4 a0 = make_float4(f[0].x, f[1].x, f[2].x, f[3].x);
            float4 a1 = make_float4(f[0].y, f[1].y, f[2].y, f[3].y);
            float4 b0 = make_float4(f[4].x, f[5].x, f[6].x, f[7].x);
            float4 b1 = make_float4(f[4].y, f[5].y, f[6].y, f[7].y);
            sxA[2 * lane]     = *reinterpret_cast<ulonglong2*>(&a0);
            sxA[2 * lane + 1] = *reinterpret_cast<ulonglong2*>(&a1);
            sxB[2 * lane]     = *reinterpret_cast<ulonglong2*>(&b0);
            sxB[2 * lane + 1] = *reinterpret_cast<ulonglong2*>(&b1);
        }
        __syncwarp();

        unsigned long long acc[8];
        #pragma unroll
        for (int i = 0; i < 8; i++) acc[i] = 0ull;

        #pragma unroll 4
        for (int k = 0; k < 64; k++) {
            float2 w = sW[k * 32 + lane];
            unsigned long long wxx = dup_f32(w.x);
            unsigned long long wyy = dup_f32(w.y);
            ulonglong2 a = sxA[k];
            ulonglong2 b = sxB[k];
            fma2(acc[0], a.x, wxx);
            fma2(acc[1], a.y, wxx);
            fma2(acc[2], a.x, wyy);
            fma2(acc[3], a.y, wyy);
            fma2(acc[4], b.x, wxx);
            fma2(acc[5], b.y, wxx);
            fma2(acc[6], b.x, wyy);
            fma2(acc[7], b.y, wyy);
        }

        #pragma unroll
        for (int h = 0; h < 4; h++) {
            int ia = (h < 2) ? h : h + 2;
            int ib = ia + 2;
            float l0, h0, l1, h1;
            unpack2(acc[ia], l0, h0);
            unpack2(acc[ib], l1, h1);
            emit_row(row0 + 2 * h,     lane, l0, l1);
            emit_row(row0 + 2 * h + 1, lane, h0, h1);
        }
        __syncwarp();
    }
}

// ---------------- gather-sum aggregation (bf16 messages, fp32 accumulate) ---------
// out[d] = dinv[d] * ( sum_{s in N(d)} P[s] + P[d] ) + b ; optional relu
template <int RELU, int OUT_BF16>
__global__ void k_gather(void* __restrict__ Hout, const float* __restrict__ bias) {
    int widx = (blockIdx.x * blockDim.x + threadIdx.x) >> 5;
    if (widx >= N_NODES) return;
    int lane = threadIdx.x & 31;

    float dn = g_dinv[widx];
    int start = g_rowptr[widx];
    int cnt = g_deg[widx];
    int end = start + cnt;

    float2 acc = __bfloat1622float2(g_P[widx * 32 + lane]);   // self term

    for (int p = start; p < end; p += 4) {
        int4 s4 = *reinterpret_cast<const int4*>(g_csc + p);  // aligned
        float2 v0 = __bfloat1622float2(g_P[(size_t)s4.x * 32 + lane]);
        float2 v1 = __bfloat1622float2(g_P[(size_t)s4.y * 32 + lane]);
        float2 v2 = __bfloat1622float2(g_P[(size_t)s4.z * 32 + lane]);
        float2 v3 = __bfloat1622float2(g_P[(size_t)s4.w * 32 + lane]);
        int rem = end - p;
        acc.x += v0.x; acc.y += v0.y;
        if (rem > 1) { acc.x += v1.x; acc.y += v1.y; }
        if (rem > 2) { acc.x += v2.x; acc.y += v2.y; }
        if (rem > 3) { acc.x += v3.x; acc.y += v3.y; }
    }

    float2 b = reinterpret_cast<const float2*>(bias)[lane];
    float ox = dn * acc.x + b.x;
    float oy = dn * acc.y + b.y;
    if (RELU) { ox = fmaxf(ox, 0.f); oy = fmaxf(oy, 0.f); }
    if (OUT_BF16)
        ((__nv_bfloat162*)Hout)[widx * 32 + lane] = __floats2bfloat162_rn(ox, oy);
    else
        ((float2*)Hout)[widx * 32 + lane] = make_float2(ox, oy);
}

// ---------------- pool (mean per graph) + final linear ----------------
__device__ __forceinline__ int lbound(const int* __restrict__ a, int n, int key) {
    int lo = 0, hi = n;
    while (lo < hi) {
        int m = (lo + hi) >> 1;
        if (a[m] < key) lo = m + 1; else hi = m;
    }
    return lo;
}

__global__ void k_pool(const int* __restrict__ batch,
                       const float* __restrict__ Wl, const float* __restrict__ bl,
                       float* __restrict__ out) {
    __shared__ float sm[256];
    int g = blockIdx.x;
    int t = threadIdx.x;
    int lo = lbound(batch, N_NODES, g);
    int hi = lbound(batch, N_NODES, g + 1);

    int col = t & 63;
    int part = t >> 6;
    float s = 0.f;
    for (int n = lo + part; n < hi; n += 4) s += g_H2[(size_t)n * 64 + col];
    sm[t] = s;
    __syncthreads();
    if (t < 64) {
        float v = sm[t] + sm[t + 64] + sm[t + 128] + sm[t + 192];
        int cnt = hi - lo;
        v /= (float)(cnt > 0 ? cnt : 1);
        sm[t] = v * Wl[t];
    }
    __syncthreads();
    if (t == 0) {
        float r = 0.f;
        #pragma unroll
        for (int c = 0; c < 64; c++) r += sm[c];
        out[g] = r + bl[0];
    }
}

// ---------------- launch ----------------
extern "C" void kernel_launch(void* const* d_in, const int* in_sizes, int n_in,
                              void* d_out, int out_size) {
    const float* x     = (const float*)d_in[0];
    const int*   eidx  = (const int*)d_in[1];
    const int*   batch = (const int*)d_in[2];
    const float* W1    = (const float*)d_in[3];
    const float* b1    = (const float*)d_in[4];
    const float* W2    = (const float*)d_in[5];
    const float* b2    = (const float*)d_in[6];
    const float* Wl    = (const float*)d_in[7];
    const float* bl    = (const float*)d_in[8];
    float* out = (float*)d_out;

    const int* src = eidx;
    const int* dst = eidx + N_EDGES;

    float *H1p, *H2p;  // only for typed args where needed
    (void)H1p; (void)H2p;

    // gemm1 needs 64KB dynamic smem (idempotent; not a graph node)
    cudaFuncSetAttribute(k_gemm1, cudaFuncAttributeMaxDynamicSharedMemorySize, 65536);

    int nThreads = 256;
    int nbNodes = (N_NODES + nThreads - 1) / nThreads;
    int nbEdges = (N_EDGES + nThreads - 1) / nThreads;

    // --- CSC build ---
    k_zero_deg<<<nbNodes, nThreads>>>();
    k_count<<<nbEdges, nThreads>>>(dst);
    k_scanA<<<SCAN_NB, SCAN_B>>>();
    k_scanB<<<1, 128>>>();
    k_scanC<<<nbNodes, nThreads>>>();
    k_fill<<<nbEdges, nThreads>>>(src, dst);

    // --- layer 1 ---
    k_gemm1<<<444, 256, 65536>>>(x, W1);
    float* H1v; cudaGetSymbolAddress((void**)&H1v, g_H1);
    k_gather<1, 1><<<(N_NODES * 32 + 255) / 256, 256>>>((void*)H1v, b1);

    // --- layer 2 ---
    k_gemm2<<<592, 256>>>(W2);
    float* H2v; cudaGetSymbolAddress((void**)&H2v, g_H2);
    k_gather<0, 0><<<(N_NODES * 32 + 255) / 256, 256>>>((void*)H2v, b2);

    // --- pool + head ---
    k_pool<<<N_GRAPHS, 256>>>(batch, Wl, bl, out);
}

// round 6
// speedup vs baseline: 1.4550x; 1.0434x over previous
#include <cuda_runtime.h>
#include <cuda_bf16.h>
#include <stdint.h>

#define N_NODES  100000
#define N_EDGES  3200000
#define N_FEAT   128
#define HIDDEN   64
#define N_GRAPHS 256

// Padded CSC capacity: E + 3 per node + 8 slack for unroll-8 overread
#define CSC_CAP  (N_EDGES + 4 * N_NODES + 8)

// ---------------- device scratch ----------------
__device__ __align__(16) static __nv_bfloat162 g_P [N_NODES * 32];  // 12.8 MB messages
__device__ __align__(16) static __nv_bfloat162 g_H1[N_NODES * 32];  // 12.8 MB layer-1 out
__device__ __align__(16) static __nv_bfloat162 g_H2[N_NODES * 32];  // 12.8 MB layer-2 out
__device__ __align__(16) static int   g_csc[CSC_CAP];               // pad slots stay 0
__device__              static int   g_deg[N_NODES];
__device__              static int   g_rowptr[N_NODES];
__device__              static int   g_cursor[N_NODES];
__device__              static float g_dinv[N_NODES];
__device__              static int   g_bsum[128];

// ---------------- init ----------------
__global__ void k_zero_deg() {
    int i = blockIdx.x * blockDim.x + threadIdx.x;
    if (i < N_NODES) g_deg[i] = 0;
}

// ---------------- degree histogram, 4 edges/thread ----------------
__global__ void k_count(const int4* __restrict__ dst4) {
    int i = blockIdx.x * blockDim.x + threadIdx.x;
    if (i < N_EDGES / 4) {
        int4 d = dst4[i];
        atomicAdd(&g_deg[d.x], 1);
        atomicAdd(&g_deg[d.y], 1);
        atomicAdd(&g_deg[d.z], 1);
        atomicAdd(&g_deg[d.w], 1);
    }
}

// ---------------- exclusive scan of padded degrees (+ dinv fused) ----------------
#define SCAN_B 1024
#define SCAN_NB ((N_NODES + SCAN_B - 1) / SCAN_B)   // 98

__global__ void k_scanA() {
    __shared__ int sm[SCAN_B];
    int i = blockIdx.x * SCAN_B + threadIdx.x;
    int v = 0;
    if (i < N_NODES) {
        int d = g_deg[i];
        g_dinv[i] = rsqrtf((float)(d + 1));          // fused dinv (self-loop +1)
        v = (d + 3) & ~3;                            // pad segment to multiple of 4
    }
    sm[threadIdx.x] = v;
    __syncthreads();
    #pragma unroll
    for (int off = 1; off < SCAN_B; off <<= 1) {
        int t = (threadIdx.x >= off) ? sm[threadIdx.x - off] : 0;
        __syncthreads();
        sm[threadIdx.x] += t;
        __syncthreads();
    }
    int inc = sm[threadIdx.x];
    if (i < N_NODES) g_rowptr[i] = inc - v;
    if (threadIdx.x == SCAN_B - 1) g_bsum[blockIdx.x] = inc;
}

__global__ void k_scanB() {
    __shared__ int sm[128];
    int t = threadIdx.x;
    int v = (t < SCAN_NB) ? g_bsum[t] : 0;
    sm[t] = v;
    __syncthreads();
    #pragma unroll
    for (int off = 1; off < 128; off <<= 1) {
        int u = (t >= off) ? sm[t - off] : 0;
        __syncthreads();
        sm[t] += u;
        __syncthreads();
    }
    if (t < SCAN_NB) g_bsum[t] = sm[t] - v;
}

__global__ void k_scanC() {
    int i = blockIdx.x * blockDim.x + threadIdx.x;
    if (i < N_NODES) {
        int r = g_rowptr[i] + g_bsum[i >> 10];
        g_rowptr[i] = r;
        g_cursor[i] = r;
    }
}

// ---------------- CSC bucket fill, 4 edges/thread ----------------
__global__ void k_fill(const int4* __restrict__ src4, const int4* __restrict__ dst4) {
    int i = blockIdx.x * blockDim.x + threadIdx.x;
    if (i < N_EDGES / 4) {
        int4 s = src4[i];
        int4 d = dst4[i];
        g_csc[atomicAdd(&g_cursor[d.x], 1)] = s.x;
        g_csc[atomicAdd(&g_cursor[d.y], 1)] = s.y;
        g_csc[atomicAdd(&g_cursor[d.z], 1)] = s.z;
        g_csc[atomicAdd(&g_cursor[d.w], 1)] = s.w;
    }
}

// ---------------- f32x2 helpers ----------------
__device__ __forceinline__ unsigned long long dup_f32(float x) {
    unsigned long long r;
    unsigned xb = __float_as_uint(x);
    asm("mov.b64 %0, {%1, %1};" : "=l"(r) : "r"(xb));
    return r;
}
__device__ __forceinline__ void fma2(unsigned long long& acc, unsigned long long a,
                                     unsigned long long b) {
    asm("fma.rn.f32x2 %0, %1, %2, %0;" : "+l"(acc) : "l"(a), "l"(b));
}
__device__ __forceinline__ void unpack2(unsigned long long v, float& lo, float& hi) {
    asm("mov.b64 {%0, %1}, %2;" : "=f"(lo), "=f"(hi) : "l"(v));
}

__device__ __forceinline__ void emit_row(int row, int lane, float c0, float c1) {
    if (row < N_NODES) {
        float s = g_dinv[row];
        g_P[row * 32 + lane] = __floats2bfloat162_rn(c0 * s, c1 * s);
    }
}

// ---------------- GEMM1: P = (X[fp32, K=128] @ W1) * dinv, bf16 out ----------------
__global__ void k_gemm1(const float* __restrict__ X, const float* __restrict__ W) {
    extern __shared__ unsigned char dyn[];
    float2*     sW = (float2*)dyn;                         // 128*32 float2 = 32KB
    ulonglong2* sx = (ulonglong2*)(dyn + 32768);           // 8 warps * 256 entries = 32KB
    const float2* W2 = (const float2*)W;
    for (int t = threadIdx.x; t < 128 * 32; t += 256) sW[t] = W2[t];
    __syncthreads();

    int warp = threadIdx.x >> 5, lane = threadIdx.x & 31;
    ulonglong2* sxA = sx + warp * 256;   // rows 0-3, [128]
    ulonglong2* sxB = sxA + 128;         // rows 4-7, [128]
    const int NG = (N_NODES + 63) >> 6;

    for (int g = blockIdx.x; g < NG; g += gridDim.x) {
        int row0 = g * 64 + warp * 8;
        #pragma unroll
        for (int j = 0; j < 4; j++) {
            int k = lane + 32 * j;
            float v[8];
            #pragma unroll
            for (int r = 0; r < 8; r++) {
                int rr = row0 + r; if (rr >= N_NODES) rr = N_NODES - 1;
                v[r] = X[(size_t)rr * 128 + k];
            }
            float4 fa = make_float4(v[0], v[1], v[2], v[3]);
            float4 fb = make_float4(v[4], v[5], v[6], v[7]);
            sxA[k] = *reinterpret_cast<ulonglong2*>(&fa);
            sxB[k] = *reinterpret_cast<ulonglong2*>(&fb);
        }
        __syncwarp();

        unsigned long long acc[8];
        #pragma unroll
        for (int i = 0; i < 8; i++) acc[i] = 0ull;

        #pragma unroll 4
        for (int k = 0; k < 128; k++) {
            float2 w = sW[k * 32 + lane];
            unsigned long long wxx = dup_f32(w.x);
            unsigned long long wyy = dup_f32(w.y);
            ulonglong2 a = sxA[k];
            ulonglong2 b = sxB[k];
            fma2(acc[0], a.x, wxx);
            fma2(acc[1], a.y, wxx);
            fma2(acc[2], a.x, wyy);
            fma2(acc[3], a.y, wyy);
            fma2(acc[4], b.x, wxx);
            fma2(acc[5], b.y, wxx);
            fma2(acc[6], b.x, wyy);
            fma2(acc[7], b.y, wyy);
        }

        #pragma unroll
        for (int h = 0; h < 4; h++) {
            int ia = (h < 2) ? h : h + 2;
            int ib = ia + 2;
            float l0, h0, l1, h1;
            unpack2(acc[ia], l0, h0);
            unpack2(acc[ib], l1, h1);
            emit_row(row0 + 2 * h,     lane, l0, l1);
            emit_row(row0 + 2 * h + 1, lane, h0, h1);
        }
        __syncwarp();
    }
}

// ---------------- GEMM2: P = (H1[bf16, K=64] @ W2) * dinv, bf16 out ----------------
__global__ void k_gemm2(const float* __restrict__ W) {
    __shared__ float2     sW[64 * 32];      // 16KB
    __shared__ ulonglong2 sx[8 * 128];      // 16KB
    const float2* W2 = (const float2*)W;
    for (int t = threadIdx.x; t < 64 * 32; t += 256) sW[t] = W2[t];
    __syncthreads();

    int warp = threadIdx.x >> 5, lane = threadIdx.x & 31;
    ulonglong2* sxA = sx + warp * 128;
    ulonglong2* sxB = sxA + 64;
    const int NG = (N_NODES + 63) >> 6;

    for (int g = blockIdx.x; g < NG; g += gridDim.x) {
        int row0 = g * 64 + warp * 8;
        {
            float2 f[8];
            #pragma unroll
            for (int r = 0; r < 8; r++) {
                int rr = row0 + r; if (rr >= N_NODES) rr = N_NODES - 1;
                f[r] = __bfloat1622float2(g_H1[rr * 32 + lane]);
            }
            float4 a0 = make_float4(f[0].x, f[1].x, f[2].x, f[3].x);
            float4 a1 = make_float4(f[0].y, f[1].y, f[2].y, f[3].y);
            float4 b0 = make_float4(f[4].x, f[5].x, f[6].x, f[7].x);
            float4 b1 = make_float4(f[4].y, f[5].y, f[6].y, f[7].y);
            sxA[2 * lane]     = *reinterpret_cast<ulonglong2*>(&a0);
            sxA[2 * lane + 1] = *reinterpret_cast<ulonglong2*>(&a1);
            sxB[2 * lane]     = *reinterpret_cast<ulonglong2*>(&b0);
            sxB[2 * lane + 1] = *reinterpret_cast<ulonglong2*>(&b1);
        }
        __syncwarp();

        unsigned long long acc[8];
        #pragma unroll
        for (int i = 0; i < 8; i++) acc[i] = 0ull;

        #pragma unroll 4
        for (int k = 0; k < 64; k++) {
            float2 w = sW[k * 32 + lane];
            unsigned long long wxx = dup_f32(w.x);
            unsigned long long wyy = dup_f32(w.y);
            ulonglong2 a = sxA[k];
            ulonglong2 b = sxB[k];
            fma2(acc[0], a.x, wxx);
            fma2(acc[1], a.y, wxx);
            fma2(acc[2], a.x, wyy);
            fma2(acc[3], a.y, wyy);
            fma2(acc[4], b.x, wxx);
            fma2(acc[5], b.y, wxx);
            fma2(acc[6], b.x, wyy);
            fma2(acc[7], b.y, wyy);
        }

        #pragma unroll
        for (int h = 0; h < 4; h++) {
            int ia = (h < 2) ? h : h + 2;
            int ib = ia + 2;
            float l0, h0, l1, h1;
            unpack2(acc[ia], l0, h0);
            unpack2(acc[ib], l1, h1);
            emit_row(row0 + 2 * h,     lane, l0, l1);
            emit_row(row0 + 2 * h + 1, lane, h0, h1);
        }
        __syncwarp();
    }
}

// ---------------- gather-sum aggregation (bf16 messages, fp32 accumulate) ---------
// out[d] = dinv[d] * ( sum_{s in N(d)} P[s] + P[d] ) + b ; optional relu
// unroll-8: loads unconditional (in-bounds via CSC slack + zero padding), adds guarded.
template <int RELU>
__global__ void k_gather(__nv_bfloat162* __restrict__ Hout,
                         const float* __restrict__ bias) {
    int widx = (blockIdx.x * blockDim.x + threadIdx.x) >> 5;
    if (widx >= N_NODES) return;
    int lane = threadIdx.x & 31;

    float dn = g_dinv[widx];
    int start = g_rowptr[widx];
    int cnt = g_deg[widx];
    int end = start + cnt;

    float2 acc = __bfloat1622float2(g_P[widx * 32 + lane]);   // self term

    for (int p = start; p < end; p += 8) {
        int4 sa = *reinterpret_cast<const int4*>(g_csc + p);
        int4 sb = *reinterpret_cast<const int4*>(g_csc + p + 4);
        float2 v0 = __bfloat1622float2(g_P[(size_t)sa.x * 32 + lane]);
        float2 v1 = __bfloat1622float2(g_P[(size_t)sa.y * 32 + lane]);
        float2 v2 = __bfloat1622float2(g_P[(size_t)sa.z * 32 + lane]);
        float2 v3 = __bfloat1622float2(g_P[(size_t)sa.w * 32 + lane]);
        float2 v4 = __bfloat1622float2(g_P[(size_t)sb.x * 32 + lane]);
        float2 v5 = __bfloat1622float2(g_P[(size_t)sb.y * 32 + lane]);
        float2 v6 = __bfloat1622float2(g_P[(size_t)sb.z * 32 + lane]);
        float2 v7 = __bfloat1622float2(g_P[(size_t)sb.w * 32 + lane]);
        int rem = end - p;
        acc.x += v0.x; acc.y += v0.y;
        if (rem > 1) { acc.x += v1.x; acc.y += v1.y; }
        if (rem > 2) { acc.x += v2.x; acc.y += v2.y; }
        if (rem > 3) { acc.x += v3.x; acc.y += v3.y; }
        if (rem > 4) { acc.x += v4.x; acc.y += v4.y; }
        if (rem > 5) { acc.x += v5.x; acc.y += v5.y; }
        if (rem > 6) { acc.x += v6.x; acc.y += v6.y; }
        if (rem > 7) { acc.x += v7.x; acc.y += v7.y; }
    }

    float2 b = reinterpret_cast<const float2*>(bias)[lane];
    float ox = dn * acc.x + b.x;
    float oy = dn * acc.y + b.y;
    if (RELU) { ox = fmaxf(ox, 0.f); oy = fmaxf(oy, 0.f); }
    Hout[widx * 32 + lane] = __floats2bfloat162_rn(ox, oy);
}

// ---------------- pool (mean per graph, bf16 in) + final linear ----------------
__device__ __forceinline__ int lbound(const int* __restrict__ a, int n, int key) {
    int lo = 0, hi = n;
    while (lo < hi) {
        int m = (lo + hi) >> 1;
        if (a[m] < key) lo = m + 1; else hi = m;
    }
    return lo;
}

__global__ void k_pool(const int* __restrict__ batch,
                       const float* __restrict__ Wl, const float* __restrict__ bl,
                       float* __restrict__ out) {
    __shared__ float2 sm[256];               // 8 partitions x 32 col-pairs
    int g = blockIdx.x;
    int t = threadIdx.x;                     // 256 threads
    int lo = lbound(batch, N_NODES, g);
    int hi = lbound(batch, N_NODES, g + 1);

    int cp   = t & 31;                       // col pair 0..31
    int part = t >> 5;                       // 8 partitions
    float2 s = make_float2(0.f, 0.f);
    for (int n = lo + part; n < hi; n += 8) {
        float2 v = __bfloat1622float2(g_H2[(size_t)n * 32 + cp]);
        s.x += v.x; s.y += v.y;
    }
    sm[t] = s;
    __syncthreads();
    if (t < 32) {
        float2 v = sm[t];
        #pragma unroll
        for (int p = 1; p < 8; p++) {
            float2 u = sm[t + 32 * p];
            v.x += u.x; v.y += u.y;
        }
        int cnt = hi - lo;
        float inv = 1.f / (float)(cnt > 0 ? cnt : 1);
        float2 w = reinterpret_cast<const float2*>(Wl)[t];
        sm[t] = make_float2(v.x * inv * w.x + v.y * inv * w.y, 0.f);
    }
    __syncthreads();
    if (t == 0) {
        float r = 0.f;
        #pragma unroll
        for (int c = 0; c < 32; c++) r += sm[c].x;
        out[g] = r + bl[0];
    }
}

// ---------------- launch (single stream, R3-proven structure) ----------------
extern "C" void kernel_launch(void* const* d_in, const int* in_sizes, int n_in,
                              void* d_out, int out_size) {
    const float* x     = (const float*)d_in[0];
    const int*   eidx  = (const int*)d_in[1];
    const int*   batch = (const int*)d_in[2];
    const float* W1    = (const float*)d_in[3];
    const float* b1    = (const float*)d_in[4];
    const float* W2    = (const float*)d_in[5];
    const float* b2    = (const float*)d_in[6];
    const float* Wl    = (const float*)d_in[7];
    const float* bl    = (const float*)d_in[8];
    float* out = (float*)d_out;

    const int4* src4 = (const int4*)eidx;
    const int4* dst4 = (const int4*)(eidx + N_EDGES);

    cudaFuncSetAttribute(k_gemm1, cudaFuncAttributeMaxDynamicSharedMemorySize, 65536);

    __nv_bfloat162* H1v; cudaGetSymbolAddress((void**)&H1v, g_H1);
    __nv_bfloat162* H2v; cudaGetSymbolAddress((void**)&H2v, g_H2);

    int nThreads = 256;
    int nbNodes = (N_NODES + nThreads - 1) / nThreads;
    int nbEdge4 = (N_EDGES / 4 + nThreads - 1) / nThreads;

    // --- CSC build ---
    k_zero_deg<<<nbNodes, nThreads>>>();
    k_count<<<nbEdge4, nThreads>>>(dst4);
    k_scanA<<<SCAN_NB, SCAN_B>>>();
    k_scanB<<<1, 128>>>();
    k_scanC<<<nbNodes, nThreads>>>();
    k_fill<<<nbEdge4, nThreads>>>(src4, dst4);

    // --- layer 1 ---
    k_gemm1<<<444, 256, 65536>>>(x, W1);
    k_gather<1><<<(N_NODES * 32 + 255) / 256, 256>>>(H1v, b1);

    // --- layer 2 ---
    k_gemm2<<<592, 256>>>(W2);
    k_gather<0><<<(N_NODES * 32 + 255) / 256, 256>>>(H2v, b2);

    // --- pool + head ---
    k_pool<<<N_GRAPHS, 256>>>(batch, Wl, bl, out);
}